// round 14
// baseline (speedup 1.0000x reference)
#include <cuda_runtime.h>
#include <cuda_bf16.h>
#include <cuda_fp8.h>
#include <cstdint>
#include <cstddef>

#define BATCH 8
#define SEQ   2048
#define DIM   1024
#define MTOT  (BATCH*SEQ)   // 16384
#define NQKV  (3*DIM)       // 3072
#define KTILES (SEQ/128)    // 16 k-tiles per attention row

#define BM 128
#define BN 128
#define BK 64                             // bf16 elements per k-step
#define BKF 128                           // fp8 elements per k-step (same bytes)
#define KSTRIDE 72                        // bf16 halves per smem row (64 + 8 pad) = 144 B
#define ROWB 144                          // bytes per smem tile row (both dtypes)
#define A_TILE_BYTES (BM*ROWB)            // 18432
#define STAGE_BYTES (2*A_TILE_BYTES)      // 36864
#define STAGES 3

// ---- scratch (device globals; allocation-free per harness rules) ----
__device__ __nv_bfloat16 g_xb[(size_t)MTOT*DIM];
__device__ __nv_bfloat16 g_Wqkvb[(size_t)NQKV*DIM];
__device__ __nv_bfloat16 g_Wob[DIM*DIM];
__device__ float         g_bqkv[NQKV];
__device__ __nv_bfloat16 g_QKV[(size_t)MTOT*NQKV];
__device__ uint8_t       g_Qf [(size_t)MTOT*DIM];
__device__ uint8_t       g_Kf [(size_t)MTOT*DIM];
__device__ uint8_t       g_Vtf[(size_t)MTOT*DIM];
__device__ uint8_t       g_P  [(size_t)BATCH*SEQ*SEQ];
__device__ float         g_rpart[(size_t)BATCH*KTILES*SEQ];
__device__ float         g_rinv [(size_t)BATCH*SEQ];
__device__ __nv_bfloat16 g_Wt[(size_t)MTOT*DIM];

// ---- helpers ----
__device__ __forceinline__ void cp16(uint32_t saddr, const void* gmem) {
    asm volatile("cp.async.cg.shared.global [%0], [%1], 16;\n" :: "r"(saddr), "l"(gmem));
}
__device__ __forceinline__ void cp_commit() { asm volatile("cp.async.commit_group;\n"); }
template<int N> __device__ __forceinline__ void cp_wait() {
    asm volatile("cp.async.wait_group %0;\n" :: "n"(N));
}
__device__ __forceinline__ void ldsm_x4(uint32_t& r0, uint32_t& r1, uint32_t& r2, uint32_t& r3,
                                        uint32_t addr) {
    asm volatile("ldmatrix.sync.aligned.m8n8.x4.shared.b16 {%0,%1,%2,%3}, [%4];"
                 : "=r"(r0), "=r"(r1), "=r"(r2), "=r"(r3) : "r"(addr));
}
__device__ __forceinline__ void mma_bf16(float c[4], const uint32_t a[4], const uint32_t b[2]) {
    asm("mma.sync.aligned.m16n8k16.row.col.f32.bf16.bf16.f32 "
        "{%0,%1,%2,%3},{%4,%5,%6,%7},{%8,%9},{%0,%1,%2,%3};"
        : "+f"(c[0]), "+f"(c[1]), "+f"(c[2]), "+f"(c[3])
        : "r"(a[0]), "r"(a[1]), "r"(a[2]), "r"(a[3]), "r"(b[0]), "r"(b[1]));
}
__device__ __forceinline__ void mma_e4m3(float c[4], const uint32_t a[4], const uint32_t b[2]) {
    asm("mma.sync.aligned.m16n8k32.row.col.f32.e4m3.e4m3.f32 "
        "{%0,%1,%2,%3},{%4,%5,%6,%7},{%8,%9},{%0,%1,%2,%3};"
        : "+f"(c[0]), "+f"(c[1]), "+f"(c[2]), "+f"(c[3])
        : "r"(a[0]), "r"(a[1]), "r"(a[2]), "r"(a[3]), "r"(b[0]), "r"(b[1]));
}

// ======== shared epilogue store ========
template<typename OutT>
__device__ __forceinline__ void store_pair(OutT* C, long off, float v0, float v1) {
    if constexpr (sizeof(OutT) == 1) {
        *reinterpret_cast<__nv_fp8x2_storage_t*>(&C[off]) =
            __nv_cvt_float2_to_fp8x2(make_float2(v0, v1), __NV_SATFINITE, __NV_E4M3);
    } else if constexpr (sizeof(OutT) == 2) {
        *reinterpret_cast<__nv_bfloat162*>(&C[off]) = __floats2bfloat162_rn(v0, v1);
    } else {
        *reinterpret_cast<float2*>(&C[off]) = make_float2(v0, v1);
    }
}

// ---- bf16 NT GEMM (proven R8 config): C = A[M,K] B[N,K]^T * scale (+bias)(+resid) ----
template<typename OutT, bool HAS_BIAS, bool HAS_RESID>
__global__ __launch_bounds__(128, 2) void gemm_bf(
    const __nv_bfloat16* __restrict__ A, const __nv_bfloat16* __restrict__ B,
    const float* __restrict__ bias, const float* __restrict__ resid,
    OutT* __restrict__ C,
    int lda, int ldb, int ldc, int K, float scale,
    long sA, long sB, long sC)
{
    extern __shared__ __align__(16) uint8_t smem[];

    const int bz = blockIdx.z;
    A += (long)bz * sA; B += (long)bz * sB; C += (long)bz * sC;

    const int m0 = blockIdx.y * BM;
    const int n0 = blockIdx.x * BN;
    const int tid  = threadIdx.x;
    const int wid  = tid >> 5;
    const int lane = tid & 31;
    const int wm = (wid >> 1) * 64;
    const int wn = (wid & 1) * 64;
    const int lg = lane >> 2;
    const int lq = lane & 3;

    const int lr = tid >> 3;
    const int lc = (tid & 7) * 8;      // bf16 elements

    const int a_row = wm + (lane & 15);
    const int a_kB  = (lane >> 4) * 16;               // bytes
    const int b_row = wn + (lane & 7) + ((lane >> 4) & 1) * 8;
    const int b_kB  = ((lane >> 3) & 1) * 16;         // bytes

    const uint32_t smem_base = (uint32_t)__cvta_generic_to_shared(smem);

    float acc[4][8][4];
#pragma unroll
    for (int i = 0; i < 4; i++)
#pragma unroll
        for (int j = 0; j < 8; j++)
#pragma unroll
            for (int r = 0; r < 4; r++) acc[i][j][r] = 0.f;

    const int KT = K / BK;

    auto load_stage = [&](int buf, int kt) {
        const int k0 = kt * BK;
        const uint32_t as = smem_base + buf * STAGE_BYTES;
        const uint32_t bs = as + A_TILE_BYTES;
#pragma unroll
        for (int p = 0; p < 8; p++) {
            int row = lr + p * 16;
            cp16(as + row * ROWB + lc * 2, A + (long)(m0 + row) * lda + k0 + lc);
            cp16(bs + row * ROWB + lc * 2, B + (long)(n0 + row) * ldb + k0 + lc);
        }
        cp_commit();
    };

    load_stage(0, 0);
    load_stage(1, 1);

    for (int kt = 0; kt < KT; kt++) {
        const int buf = kt % STAGES;
        cp_wait<1>();
        __syncthreads();
        if (kt + 2 < KT) load_stage((kt + 2) % STAGES, kt + 2);

        const uint32_t as = smem_base + buf * STAGE_BYTES;
        const uint32_t bs = as + A_TILE_BYTES;

#pragma unroll
        for (int s = 0; s < 4; s++) {
            uint32_t af[4][4];
            uint32_t bfr[8][2];
#pragma unroll
            for (int i = 0; i < 4; i++) {
                uint32_t addr = as + (a_row + i * 16) * ROWB + s * 32 + a_kB;
                ldsm_x4(af[i][0], af[i][1], af[i][2], af[i][3], addr);
            }
#pragma unroll
            for (int jp = 0; jp < 4; jp++) {
                uint32_t addr = bs + (b_row + jp * 16) * ROWB + s * 32 + b_kB;
                ldsm_x4(bfr[jp * 2][0], bfr[jp * 2][1],
                        bfr[jp * 2 + 1][0], bfr[jp * 2 + 1][1], addr);
            }
#pragma unroll
            for (int i = 0; i < 4; i++)
#pragma unroll
                for (int j = 0; j < 8; j++)
                    mma_bf16(acc[i][j], af[i], bfr[j]);
        }
    }

#pragma unroll
    for (int i = 0; i < 4; i++) {
        int r = m0 + wm + i * 16 + lg;
#pragma unroll
        for (int j = 0; j < 8; j++) {
            int c = n0 + wn + j * 8 + lq * 2;
            float v0 = acc[i][j][0] * scale;
            float v1 = acc[i][j][1] * scale;
            float v2 = acc[i][j][2] * scale;
            float v3 = acc[i][j][3] * scale;
            if (HAS_BIAS) {
                float b0 = bias[c], b1 = bias[c + 1];
                v0 += b0; v1 += b1; v2 += b0; v3 += b1;
            }
            if (HAS_RESID) {
                v0 += resid[(long)r * ldc + c];
                v1 += resid[(long)r * ldc + c + 1];
                v2 += resid[(long)(r + 8) * ldc + c];
                v3 += resid[(long)(r + 8) * ldc + c + 1];
            }
            store_pair(C, (long)r * ldc + c, v0, v1);
            store_pair(C, (long)(r + 8) * ldc + c, v2, v3);
        }
    }
}

// ---- fp8 NT GEMM: identical structure; BK=128 fp8, mma m16n8k32.e4m3 ----
// EXP_OUT: C = exp(v*scale), per-row tile sums -> rpart. ROW_DIV: C = v*rinv[row].
template<typename OutT, bool EXP_OUT, bool ROW_DIV>
__global__ __launch_bounds__(128, 2) void gemm_f8(
    const uint8_t* __restrict__ A, const uint8_t* __restrict__ B,
    OutT* __restrict__ C,
    int lda, int ldb, int ldc, int K, float scale,
    long sA, long sB, long sC,
    float* __restrict__ rpart, const float* __restrict__ rinv)
{
    extern __shared__ __align__(16) uint8_t smem[];

    const int bz = blockIdx.z;
    A += (long)bz * sA; B += (long)bz * sB; C += (long)bz * sC;

    const int m0 = blockIdx.y * BM;
    const int n0 = blockIdx.x * BN;
    const int tid  = threadIdx.x;
    const int wid  = tid >> 5;
    const int lane = tid & 31;
    const int wm = (wid >> 1) * 64;
    const int wn = (wid & 1) * 64;
    const int lg = lane >> 2;
    const int lq = lane & 3;

    const int lr = tid >> 3;
    const int lcB = (tid & 7) * 16;    // bytes (= fp8 elements)

    const int a_row = wm + (lane & 15);
    const int a_kB  = (lane >> 4) * 16;
    const int b_row = wn + (lane & 7) + ((lane >> 4) & 1) * 8;
    const int b_kB  = ((lane >> 3) & 1) * 16;

    const uint32_t smem_base = (uint32_t)__cvta_generic_to_shared(smem);

    float acc[4][8][4];
#pragma unroll
    for (int i = 0; i < 4; i++)
#pragma unroll
        for (int j = 0; j < 8; j++)
#pragma unroll
            for (int r = 0; r < 4; r++) acc[i][j][r] = 0.f;

    const int KT = K / BKF;

    auto load_stage = [&](int buf, int kt) {
        const int k0 = kt * BKF;
        const uint32_t as = smem_base + buf * STAGE_BYTES;
        const uint32_t bs = as + A_TILE_BYTES;
#pragma unroll
        for (int p = 0; p < 8; p++) {
            int row = lr + p * 16;
            cp16(as + row * ROWB + lcB, A + (long)(m0 + row) * lda + k0 + lcB);
            cp16(bs + row * ROWB + lcB, B + (long)(n0 + row) * ldb + k0 + lcB);
        }
        cp_commit();
    };

    load_stage(0, 0);
    load_stage(1, 1);

    for (int kt = 0; kt < KT; kt++) {
        const int buf = kt % STAGES;
        cp_wait<1>();
        __syncthreads();
        if (kt + 2 < KT) load_stage((kt + 2) % STAGES, kt + 2);

        const uint32_t as = smem_base + buf * STAGE_BYTES;
        const uint32_t bs = as + A_TILE_BYTES;

#pragma unroll
        for (int s = 0; s < 4; s++) {   // 32 fp8 k per step
            uint32_t af[4][4];
            uint32_t bfr[8][2];
#pragma unroll
            for (int i = 0; i < 4; i++) {
                uint32_t addr = as + (a_row + i * 16) * ROWB + s * 32 + a_kB;
                ldsm_x4(af[i][0], af[i][1], af[i][2], af[i][3], addr);
            }
#pragma unroll
            for (int jp = 0; jp < 4; jp++) {
                uint32_t addr = bs + (b_row + jp * 16) * ROWB + s * 32 + b_kB;
                ldsm_x4(bfr[jp * 2][0], bfr[jp * 2][1],
                        bfr[jp * 2 + 1][0], bfr[jp * 2 + 1][1], addr);
            }
#pragma unroll
            for (int i = 0; i < 4; i++)
#pragma unroll
                for (int j = 0; j < 8; j++)
                    mma_e4m3(acc[i][j], af[i], bfr[j]);
        }
    }

    float rs0[4], rs1[4];
#pragma unroll
    for (int i = 0; i < 4; i++) { rs0[i] = 0.f; rs1[i] = 0.f; }

#pragma unroll
    for (int i = 0; i < 4; i++) {
        int r = m0 + wm + i * 16 + lg;
        float ri0 = 1.f, ri1 = 1.f;
        if (ROW_DIV) {
            ri0 = rinv[(long)bz * SEQ + r];
            ri1 = rinv[(long)bz * SEQ + r + 8];
        }
#pragma unroll
        for (int j = 0; j < 8; j++) {
            int c = n0 + wn + j * 8 + lq * 2;
            float v0 = acc[i][j][0] * scale;
            float v1 = acc[i][j][1] * scale;
            float v2 = acc[i][j][2] * scale;
            float v3 = acc[i][j][3] * scale;
            if (EXP_OUT) {
                v0 = __expf(v0); v1 = __expf(v1);
                v2 = __expf(v2); v3 = __expf(v3);
                rs0[i] += v0 + v1;
                rs1[i] += v2 + v3;
            }
            if (ROW_DIV) {
                v0 *= ri0; v1 *= ri0; v2 *= ri1; v3 *= ri1;
            }
            store_pair(C, (long)r * ldc + c, v0, v1);
            store_pair(C, (long)(r + 8) * ldc + c, v2, v3);
        }
    }

    if (EXP_OUT) {
        float* sf = reinterpret_cast<float*>(smem);
        const int slot = (wid & 1) * 4 + lq;
        __syncthreads();
#pragma unroll
        for (int i = 0; i < 4; i++) {
            int rr = wm + i * 16 + lg;
            sf[rr * 8 + slot]       = rs0[i];
            sf[(rr + 8) * 8 + slot] = rs1[i];
        }
        __syncthreads();
        if (tid < 128) {
            float s = 0.f;
#pragma unroll
            for (int k = 0; k < 8; k++) s += sf[tid * 8 + k];
            rpart[((long)bz * gridDim.x + blockIdx.x) * SEQ + m0 + tid] = s;
        }
    }
}

// ---- rinv[b][r] = 1 / sum_kt rpart ----
__global__ __launch_bounds__(256) void rowinv_k(const float* __restrict__ rpart,
                                                float* __restrict__ rinv)
{
    int idx = blockIdx.x * 256 + threadIdx.x;
    int b = idx / SEQ, r = idx % SEQ;
    float s = 0.f;
#pragma unroll
    for (int t = 0; t < KTILES; t++)
        s += rpart[((long)b * KTILES + t) * SEQ + r];
    rinv[idx] = 1.f / s;
}

// ---- fp32 -> bf16 convert ----
__global__ __launch_bounds__(256) void cvt_k(const float* __restrict__ in,
                                             __nv_bfloat16* __restrict__ out, int n)
{
    int i = (blockIdx.x * 256 + threadIdx.x) * 4;
    if (i < n) {
        float4 v = *reinterpret_cast<const float4*>(in + i);
        *reinterpret_cast<__nv_bfloat162*>(out + i)     = __floats2bfloat162_rn(v.x, v.y);
        *reinterpret_cast<__nv_bfloat162*>(out + i + 2) = __floats2bfloat162_rn(v.z, v.w);
    }
}

// ---- convert 3 weight matrices into concatenated bf16 buffer ----
__global__ __launch_bounds__(256) void cvt_w3_k(const float* __restrict__ w0,
                                                const float* __restrict__ w1,
                                                const float* __restrict__ w2,
                                                __nv_bfloat16* __restrict__ out)
{
    const int per = DIM * DIM / 4 / 256;
    const int mat = blockIdx.x / per;
    const int blk = blockIdx.x % per;
    const float* src = (mat == 0) ? w0 : (mat == 1) ? w1 : w2;
    int i = (blk * 256 + threadIdx.x) * 4;
    float4 v = *reinterpret_cast<const float4*>(src + i);
    __nv_bfloat16* dst = out + (size_t)mat * DIM * DIM + i;
    *reinterpret_cast<__nv_bfloat162*>(dst)     = __floats2bfloat162_rn(v.x, v.y);
    *reinterpret_cast<__nv_bfloat162*>(dst + 2) = __floats2bfloat162_rn(v.z, v.w);
}

// ---- pack 3 bias vectors into one ----
__global__ __launch_bounds__(256) void pack_bias_k(const float* __restrict__ b0,
                                                   const float* __restrict__ b1,
                                                   const float* __restrict__ b2,
                                                   float* __restrict__ out)
{
    int i = blockIdx.x * 256 + threadIdx.x;
    out[i] = (i < DIM) ? b0[i] : (i < 2 * DIM) ? b1[i - DIM] : b2[i - 2 * DIM];
}

// ---- Q,K (bf16 cols 0..2047 of QKV) -> fp8 contiguous [MTOT][DIM] each ----
__global__ __launch_bounds__(256) void qkcvt_k(const __nv_bfloat16* __restrict__ qkv,
                                               uint8_t* __restrict__ Qf,
                                               uint8_t* __restrict__ Kf)
{
    long i = (long)blockIdx.x * 256 + threadIdx.x;   // each handles 8 elems
    long r = i >> 8;
    int c8 = (int)(i & 255) * 8;                      // 0..2040
    const __nv_bfloat16* src = qkv + r * NQKV + c8;
    uint8_t* dst = (c8 < DIM) ? Qf + r * DIM + c8 : Kf + r * DIM + (c8 - DIM);
#pragma unroll
    for (int k = 0; k < 8; k += 2) {
        float2 f = __bfloat1622float2(*reinterpret_cast<const __nv_bfloat162*>(src + k));
        *reinterpret_cast<__nv_fp8x2_storage_t*>(dst + k) =
            __nv_cvt_float2_to_fp8x2(f, __NV_SATFINITE, __NV_E4M3);
    }
}

// ---- V (bf16 cols 2048..3071 of QKV) -> fp8 transposed [b][DIM][SEQ] ----
__global__ __launch_bounds__(256) void vtcvt_k(const __nv_bfloat16* __restrict__ qkv,
                                               uint8_t* __restrict__ Vt)
{
    __shared__ uint8_t t[32][36];
    const int b = blockIdx.z;
    const int x0 = blockIdx.x * 32;   // dim
    const int y0 = blockIdx.y * 32;   // seq
    const int tid = threadIdx.x;
    const int sx = tid & 31;          // dim-local
    const int sy = tid >> 5;          // 0..7 seq-local base
    const __nv_bfloat16* src = qkv + (long)b * SEQ * NQKV + 2 * DIM;
#pragma unroll
    for (int i = 0; i < 4; i++) {
        int yy = sy + i * 8;
        float f = __bfloat162float(src[(long)(y0 + yy) * NQKV + x0 + sx]);
        t[sx][yy] = (uint8_t)__nv_cvt_float_to_fp8(f, __NV_SATFINITE, __NV_E4M3);
    }
    __syncthreads();
    const int wy = tid >> 3;          // 0..31 dim row
    const int wx = (tid & 7) * 4;     // seq uchar4 chunk
    uint8_t* dst = Vt + (long)b * DIM * SEQ + (long)(x0 + wy) * SEQ + y0 + wx;
    dst[0] = t[wy][wx]; dst[1] = t[wy][wx + 1];
    dst[2] = t[wy][wx + 2]; dst[3] = t[wy][wx + 3];
}

// ---- in-place LayerNorm over rows of 1024 fp32 ----
__global__ __launch_bounds__(256) void ln_k(float* __restrict__ y,
                                            const float* __restrict__ gamma,
                                            const float* __restrict__ beta)
{
    float* p = y + (long)blockIdx.x * DIM;
    const int tid = threadIdx.x;
    float4 v = reinterpret_cast<float4*>(p)[tid];
    float s  = v.x + v.y + v.z + v.w;
    float sq = v.x * v.x + v.y * v.y + v.z * v.z + v.w * v.w;
#pragma unroll
    for (int o = 16; o; o >>= 1) {
        s  += __shfl_xor_sync(0xFFFFFFFFu, s, o);
        sq += __shfl_xor_sync(0xFFFFFFFFu, sq, o);
    }
    __shared__ float rs_[8], rq_[8];
    if ((tid & 31) == 0) { rs_[tid >> 5] = s; rq_[tid >> 5] = sq; }
    __syncthreads();
    s = 0.f; sq = 0.f;
#pragma unroll
    for (int i = 0; i < 8; i++) { s += rs_[i]; sq += rq_[i]; }
    const float mean = s * (1.f / DIM);
    const float var  = sq * (1.f / DIM) - mean * mean;
    const float inv  = rsqrtf(var + 1e-5f);
    const float4 g = reinterpret_cast<const float4*>(gamma)[tid];
    const float4 b = reinterpret_cast<const float4*>(beta)[tid];
    v.x = (v.x - mean) * inv * g.x + b.x;
    v.y = (v.y - mean) * inv * g.y + b.y;
    v.z = (v.z - mean) * inv * g.z + b.z;
    v.w = (v.w - mean) * inv * g.w + b.w;
    reinterpret_cast<float4*>(p)[tid] = v;
}

extern "C" void kernel_launch(void* const* d_in, const int* in_sizes, int n_in,
                              void* d_out, int out_size)
{
    const float* x     = (const float*)d_in[0];
    const float* Wq    = (const float*)d_in[1];
    const float* bq    = (const float*)d_in[2];
    const float* Wk    = (const float*)d_in[3];
    const float* bk    = (const float*)d_in[4];
    const float* Wv    = (const float*)d_in[5];
    const float* bv    = (const float*)d_in[6];
    const float* Wo    = (const float*)d_in[7];
    const float* bo    = (const float*)d_in[8];
    const float* gamma = (const float*)d_in[9];
    const float* beta  = (const float*)d_in[10];
    float* out = (float*)d_out;

    void *pxb, *pwqkv, *pwo, *pbqkv, *pQKV, *pQf, *pKf, *pVtf, *pP, *pW, *prp, *pri;
    cudaGetSymbolAddress(&pxb,   g_xb);
    cudaGetSymbolAddress(&pwqkv, g_Wqkvb);
    cudaGetSymbolAddress(&pwo,   g_Wob);
    cudaGetSymbolAddress(&pbqkv, g_bqkv);
    cudaGetSymbolAddress(&pQKV,  g_QKV);
    cudaGetSymbolAddress(&pQf,   g_Qf);
    cudaGetSymbolAddress(&pKf,   g_Kf);
    cudaGetSymbolAddress(&pVtf,  g_Vtf);
    cudaGetSymbolAddress(&pP,    g_P);
    cudaGetSymbolAddress(&pW,    g_Wt);
    cudaGetSymbolAddress(&prp,   g_rpart);
    cudaGetSymbolAddress(&pri,   g_rinv);
    __nv_bfloat16* xb    = (__nv_bfloat16*)pxb;
    __nv_bfloat16* Wqkvb = (__nv_bfloat16*)pwqkv;
    __nv_bfloat16* Wob   = (__nv_bfloat16*)pwo;
    float*         bqkv  = (float*)pbqkv;
    __nv_bfloat16* QKV   = (__nv_bfloat16*)pQKV;
    uint8_t*       Qf    = (uint8_t*)pQf;
    uint8_t*       Kf    = (uint8_t*)pKf;
    uint8_t*       Vtf   = (uint8_t*)pVtf;
    uint8_t*       P     = (uint8_t*)pP;
    __nv_bfloat16* Wt    = (__nv_bfloat16*)pW;
    float*         rpart = (float*)prp;
    float*         rinv  = (float*)pri;

    const int SMEM = STAGES * STAGE_BYTES;  // 110592
    cudaFuncSetAttribute((const void*)gemm_bf<__nv_bfloat16, true,  false>, cudaFuncAttributeMaxDynamicSharedMemorySize, SMEM);
    cudaFuncSetAttribute((const void*)gemm_bf<float,         true,  true >, cudaFuncAttributeMaxDynamicSharedMemorySize, SMEM);
    cudaFuncSetAttribute((const void*)gemm_f8<uint8_t,       true,  false>, cudaFuncAttributeMaxDynamicSharedMemorySize, SMEM);
    cudaFuncSetAttribute((const void*)gemm_f8<__nv_bfloat16, false, true >, cudaFuncAttributeMaxDynamicSharedMemorySize, SMEM);

    dim3 blk(128);
    dim3 blk256(256);

    // setup
    {
        int n = MTOT * DIM;
        cvt_k<<<(n / 4 + 255) / 256, blk256>>>(x, xb, n);
        cvt_w3_k<<<3 * DIM * DIM / 4 / 256, blk256>>>(Wq, Wk, Wv, Wqkvb);
        cvt_k<<<DIM * DIM / 4 / 256, blk256>>>(Wo, Wob, DIM * DIM);
        pack_bias_k<<<NQKV / 256, blk256>>>(bq, bk, bv, bqkv);
    }

    // fused QKV projection (bf16 out)
    dim3 gQKV(NQKV / BN, MTOT / BM, 1);
    gemm_bf<__nv_bfloat16, true, false><<<gQKV, blk, SMEM>>>(
        xb, Wqkvb, bqkv, nullptr, QKV, DIM, DIM, NQKV, DIM, 1.f, 0, 0, 0);

    // Q,K -> fp8 ; V -> fp8 transposed
    qkcvt_k<<<(int)((long)MTOT * 2048 / 8 / 256), blk256>>>(QKV, Qf, Kf);
    vtcvt_k<<<dim3(DIM / 32, SEQ / 32, BATCH), blk256>>>(QKV, Vtf);

    // P_unnorm = exp(Qf Kf^T / 32) (fp8 out) + per-row tile sums
    dim3 gS_(SEQ / BN, SEQ / BM, BATCH);
    gemm_f8<uint8_t, true, false><<<gS_, blk, SMEM>>>(
        Qf, Kf, P, DIM, DIM, SEQ, DIM, 0.03125f,
        (long)SEQ * DIM, (long)SEQ * DIM, (long)SEQ * SEQ, rpart, nullptr);

    // rinv = 1 / row sums
    rowinv_k<<<MTOT / 256, blk256>>>(rpart, rinv);

    // weighted = (P @ Vt^T) * rinv (fp8 NT, bf16 out)
    dim3 gW_(DIM / BN, SEQ / BM, BATCH);
    gemm_f8<__nv_bfloat16, false, true><<<gW_, blk, SMEM>>>(
        P, Vtf, Wt, SEQ, SEQ, DIM, SEQ, 1.f,
        (long)SEQ * SEQ, (long)DIM * SEQ, (long)SEQ * DIM, nullptr, rinv);

    // out = weighted Wo^T + bo + x (fp32, residual fused)
    dim3 gO_(DIM / BN, MTOT / BM, 1);
    gemm_bf<float, true, true><<<gO_, blk, SMEM>>>(
        Wt, Wob, bo, x, out, DIM, DIM, DIM, DIM, 1.f, 0, 0, 0);

    // LayerNorm
    ln_k<<<MTOT, blk256>>>(out, gamma, beta);
}

// round 15
// speedup vs baseline: 1.0255x; 1.0255x over previous
#include <cuda_runtime.h>
#include <cuda_bf16.h>
#include <cstdint>
#include <cstddef>

#define BATCH 8
#define SEQ   2048
#define DIM   1024
#define MTOT  (BATCH*SEQ)   // 16384
#define NQKV  (3*DIM)       // 3072
#define KTILES (SEQ/128)    // 16 k-tiles per attention row

#define BM 128
#define BN 128
#define BK 64
#define KSTRIDE 72                        // NT: halves per smem row (64 data + 8 pad)
#define NSTRIDE 136                       // NN B tile: 128 cols + 8 pad
#define A_TILE_HALVES (BM*KSTRIDE)        // 9216
#define STAGE_HALVES (2*A_TILE_HALVES)
#define STAGE_BYTES (STAGE_HALVES*2)      // 36864
#define STAGES 3

// ---- scratch (device globals; allocation-free per harness rules) ----
__device__ __nv_bfloat16 g_xb[(size_t)MTOT*DIM];
__device__ __nv_bfloat16 g_Wqkvb[(size_t)NQKV*DIM];
__device__ __nv_bfloat16 g_Wob[DIM*DIM];
__device__ float         g_bqkv[NQKV];
__device__ __nv_bfloat16 g_QKV[(size_t)MTOT*NQKV];
__device__ __nv_bfloat16 g_P [(size_t)BATCH*SEQ*SEQ];
__device__ float         g_rpart[(size_t)BATCH*KTILES*SEQ];
__device__ float         g_rinv [(size_t)BATCH*SEQ];
__device__ __nv_bfloat16 g_Wt[(size_t)MTOT*DIM];

// ---- helpers ----
__device__ __forceinline__ void cp16(uint32_t saddr, const void* gmem) {
    asm volatile("cp.async.cg.shared.global [%0], [%1], 16;\n" :: "r"(saddr), "l"(gmem));
}
__device__ __forceinline__ void cp_commit() { asm volatile("cp.async.commit_group;\n"); }
template<int N> __device__ __forceinline__ void cp_wait() {
    asm volatile("cp.async.wait_group %0;\n" :: "n"(N));
}
__device__ __forceinline__ void ldsm_x4(uint32_t& r0, uint32_t& r1, uint32_t& r2, uint32_t& r3,
                                        uint32_t addr) {
    asm volatile("ldmatrix.sync.aligned.m8n8.x4.shared.b16 {%0,%1,%2,%3}, [%4];"
                 : "=r"(r0), "=r"(r1), "=r"(r2), "=r"(r3) : "r"(addr));
}
__device__ __forceinline__ void ldsm_x4_t(uint32_t& r0, uint32_t& r1, uint32_t& r2, uint32_t& r3,
                                          uint32_t addr) {
    asm volatile("ldmatrix.sync.aligned.m8n8.x4.trans.shared.b16 {%0,%1,%2,%3}, [%4];"
                 : "=r"(r0), "=r"(r1), "=r"(r2), "=r"(r3) : "r"(addr));
}
__device__ __forceinline__ void mma_bf16(float c[4], const uint32_t a[4], const uint32_t b[2]) {
    asm("mma.sync.aligned.m16n8k16.row.col.f32.bf16.bf16.f32 "
        "{%0,%1,%2,%3},{%4,%5,%6,%7},{%8,%9},{%0,%1,%2,%3};"
        : "+f"(c[0]), "+f"(c[1]), "+f"(c[2]), "+f"(c[3])
        : "r"(a[0]), "r"(a[1]), "r"(a[2]), "r"(a[3]), "r"(b[0]), "r"(b[1]));
}

// ---- bf16 GEMM: C = f(A[M,K] * op(B) * scale) (+bias) (+resid) ----
// TRANSB: B [N,K] (NT) vs [K,N] (NN, ldmatrix.trans).
// EXP_OUT: C = exp(v), deterministic per-row tile sums -> rpart.
// ROW_DIV: C = v * rinv[row].
// Inner loop software-pipelines fragments (double-buffered ldmatrix).
template<typename OutT, bool HAS_BIAS, bool HAS_RESID, bool TRANSB, bool EXP_OUT, bool ROW_DIV>
__global__ __launch_bounds__(128, 2) void gemm_bf(
    const __nv_bfloat16* __restrict__ A, const __nv_bfloat16* __restrict__ B,
    const float* __restrict__ bias, const float* __restrict__ resid,
    OutT* __restrict__ C,
    int lda, int ldb, int ldc, int K, float scale,
    long sA, long sB, long sC,
    float* __restrict__ rpart, const float* __restrict__ rinv)
{
    extern __shared__ __align__(16) __nv_bfloat16 smem[];  // STAGES*(As+Bs)

    const int bz = blockIdx.z;
    A += (long)bz * sA;
    B += (long)bz * sB;
    C += (long)bz * sC;

    const int m0 = blockIdx.y * BM;
    const int n0 = blockIdx.x * BN;
    const int tid  = threadIdx.x;
    const int wid  = tid >> 5;
    const int lane = tid & 31;
    const int wm = (wid >> 1) * 64;   // 2 warps in m
    const int wn = (wid & 1) * 64;    // 2 warps in n
    const int lg = lane >> 2;
    const int lq = lane & 3;

    const int lr = tid >> 3;          // NT loader: 8 thr/row
    const int lc = (tid & 7) * 8;
    const int lr16 = tid >> 4;        // NN B loader: 16 thr/row
    const int lc16 = (tid & 15) * 8;

    const int a_row = wm + (lane & 15);
    const int a_ksel = (lane >> 4) * 8;
    const int b_row = wn + (lane & 7) + ((lane >> 4) & 1) * 8;
    const int b_ksel = ((lane >> 3) & 1) * 8;
    const int bt_krow = (lane & 7) + ((lane >> 3) & 1) * 8;
    const int bt_ncol = wn + ((lane >> 4) & 1) * 8;

    const uint32_t smem_base = (uint32_t)__cvta_generic_to_shared(smem);

    float acc[4][8][4];
#pragma unroll
    for (int i = 0; i < 4; i++)
#pragma unroll
        for (int j = 0; j < 8; j++)
#pragma unroll
            for (int r = 0; r < 4; r++) acc[i][j][r] = 0.f;

    const int KT = K / BK;

    auto load_stage = [&](int buf, int kt) {
        const int k0 = kt * BK;
        const uint32_t as = smem_base + buf * STAGE_BYTES;
        const uint32_t bs = as + A_TILE_HALVES * 2;
#pragma unroll
        for (int p = 0; p < 8; p++) {
            int row = lr + p * 16;
            cp16(as + (row * KSTRIDE + lc) * 2, A + (long)(m0 + row) * lda + k0 + lc);
        }
        if (TRANSB) {
#pragma unroll
            for (int p = 0; p < 8; p++) {
                int row = lr + p * 16;
                cp16(bs + (row * KSTRIDE + lc) * 2, B + (long)(n0 + row) * ldb + k0 + lc);
            }
        } else {
#pragma unroll
            for (int p = 0; p < 8; p++) {
                int row = lr16 + p * 8;
                cp16(bs + (row * NSTRIDE + lc16) * 2, B + (long)(k0 + row) * ldb + n0 + lc16);
            }
        }
        cp_commit();
    };

    load_stage(0, 0);
    load_stage(1, 1);

    // double-buffered fragments
    uint32_t af[2][4][4];
    uint32_t bfr[2][8][2];

    auto load_frags = [&](uint32_t as, uint32_t bs, int s, int pb) {
#pragma unroll
        for (int i = 0; i < 4; i++) {
            uint32_t addr = as + (((a_row + i * 16) * KSTRIDE) + s * 16 + a_ksel) * 2;
            ldsm_x4(af[pb][i][0], af[pb][i][1], af[pb][i][2], af[pb][i][3], addr);
        }
#pragma unroll
        for (int jp = 0; jp < 4; jp++) {
            if (TRANSB) {
                uint32_t addr = bs + (((b_row + jp * 16) * KSTRIDE) + s * 16 + b_ksel) * 2;
                ldsm_x4(bfr[pb][jp * 2][0], bfr[pb][jp * 2][1],
                        bfr[pb][jp * 2 + 1][0], bfr[pb][jp * 2 + 1][1], addr);
            } else {
                uint32_t addr = bs + (((s * 16 + bt_krow) * NSTRIDE) + bt_ncol + jp * 16) * 2;
                ldsm_x4_t(bfr[pb][jp * 2][0], bfr[pb][jp * 2][1],
                          bfr[pb][jp * 2 + 1][0], bfr[pb][jp * 2 + 1][1], addr);
            }
        }
    };

    for (int kt = 0; kt < KT; kt++) {
        const int buf = kt % STAGES;
        cp_wait<1>();
        __syncthreads();

        if (kt + 2 < KT) load_stage((kt + 2) % STAGES, kt + 2);

        const uint32_t as = smem_base + buf * STAGE_BYTES;
        const uint32_t bs = as + A_TILE_HALVES * 2;

        load_frags(as, bs, 0, 0);
#pragma unroll
        for (int s = 0; s < 4; s++) {
            const int cur = s & 1;
            if (s < 3) load_frags(as, bs, s + 1, cur ^ 1);
#pragma unroll
            for (int i = 0; i < 4; i++)
#pragma unroll
                for (int j = 0; j < 8; j++)
                    mma_bf16(acc[i][j], af[cur][i], bfr[cur][j]);
        }
    }

    // epilogue
    float rs0[4], rs1[4];
#pragma unroll
    for (int i = 0; i < 4; i++) { rs0[i] = 0.f; rs1[i] = 0.f; }

#pragma unroll
    for (int i = 0; i < 4; i++) {
        int r = m0 + wm + i * 16 + lg;
        float ri0 = 1.f, ri1 = 1.f;
        if (ROW_DIV) {
            ri0 = rinv[(long)bz * SEQ + r];
            ri1 = rinv[(long)bz * SEQ + r + 8];
        }
#pragma unroll
        for (int j = 0; j < 8; j++) {
            int c = n0 + wn + j * 8 + lq * 2;
            float v0 = acc[i][j][0] * scale;
            float v1 = acc[i][j][1] * scale;
            float v2 = acc[i][j][2] * scale;
            float v3 = acc[i][j][3] * scale;
            if (HAS_BIAS) {
                float b0 = bias[c], b1 = bias[c + 1];
                v0 += b0; v1 += b1; v2 += b0; v3 += b1;
            }
            if (HAS_RESID) {
                v0 += resid[(long)r * ldc + c];
                v1 += resid[(long)r * ldc + c + 1];
                v2 += resid[(long)(r + 8) * ldc + c];
                v3 += resid[(long)(r + 8) * ldc + c + 1];
            }
            if (EXP_OUT) {
                v0 = __expf(v0); v1 = __expf(v1);
                v2 = __expf(v2); v3 = __expf(v3);
                rs0[i] += v0 + v1;
                rs1[i] += v2 + v3;
            }
            if (ROW_DIV) {
                v0 *= ri0; v1 *= ri0;
                v2 *= ri1; v3 *= ri1;
            }
            if constexpr (sizeof(OutT) == 2) {
                *reinterpret_cast<__nv_bfloat162*>(&C[(long)r * ldc + c]) =
                    __floats2bfloat162_rn(v0, v1);
                *reinterpret_cast<__nv_bfloat162*>(&C[(long)(r + 8) * ldc + c]) =
                    __floats2bfloat162_rn(v2, v3);
            } else {
                *reinterpret_cast<float2*>(&C[(long)r * ldc + c])       = make_float2(v0, v1);
                *reinterpret_cast<float2*>(&C[(long)(r + 8) * ldc + c]) = make_float2(v2, v3);
            }
        }
    }

    if (EXP_OUT) {
        // deterministic per-row tile sums: smem [128 rows][8 slots]
        float* sf = reinterpret_cast<float*>(smem);
        const int slot = (wid & 1) * 4 + lq;
        __syncthreads();   // done with pipeline smem
#pragma unroll
        for (int i = 0; i < 4; i++) {
            int rr = wm + i * 16 + lg;
            sf[rr * 8 + slot]       = rs0[i];
            sf[(rr + 8) * 8 + slot] = rs1[i];
        }
        __syncthreads();
        if (tid < 128) {
            float s = 0.f;
#pragma unroll
            for (int k = 0; k < 8; k++) s += sf[tid * 8 + k];
            rpart[((long)bz * gridDim.x + blockIdx.x) * SEQ + m0 + tid] = s;
        }
    }
}

// ---- rinv[b][r] = 1 / sum_kt rpart[b][kt][r] ----
__global__ __launch_bounds__(256) void rowinv_k(const float* __restrict__ rpart,
                                                float* __restrict__ rinv)
{
    int idx = blockIdx.x * 256 + threadIdx.x;   // 0..MTOT-1
    int b = idx / SEQ, r = idx % SEQ;
    float s = 0.f;
#pragma unroll
    for (int t = 0; t < KTILES; t++)
        s += rpart[((long)b * KTILES + t) * SEQ + r];
    rinv[idx] = 1.f / s;
}

// ---- fp32 -> bf16 convert ----
__global__ __launch_bounds__(256) void cvt_k(const float* __restrict__ in,
                                             __nv_bfloat16* __restrict__ out, int n)
{
    int i = (blockIdx.x * 256 + threadIdx.x) * 4;
    if (i < n) {
        float4 v = *reinterpret_cast<const float4*>(in + i);
        *reinterpret_cast<__nv_bfloat162*>(out + i)     = __floats2bfloat162_rn(v.x, v.y);
        *reinterpret_cast<__nv_bfloat162*>(out + i + 2) = __floats2bfloat162_rn(v.z, v.w);
    }
}

// ---- convert 3 weight matrices into concatenated bf16 buffer ----
__global__ __launch_bounds__(256) void cvt_w3_k(const float* __restrict__ w0,
                                                const float* __restrict__ w1,
                                                const float* __restrict__ w2,
                                                __nv_bfloat16* __restrict__ out)
{
    const int per = DIM * DIM / 4 / 256;
    const int mat = blockIdx.x / per;
    const int blk = blockIdx.x % per;
    const float* src = (mat == 0) ? w0 : (mat == 1) ? w1 : w2;
    int i = (blk * 256 + threadIdx.x) * 4;
    float4 v = *reinterpret_cast<const float4*>(src + i);
    __nv_bfloat16* dst = out + (size_t)mat * DIM * DIM + i;
    *reinterpret_cast<__nv_bfloat162*>(dst)     = __floats2bfloat162_rn(v.x, v.y);
    *reinterpret_cast<__nv_bfloat162*>(dst + 2) = __floats2bfloat162_rn(v.z, v.w);
}

// ---- pack 3 bias vectors into one ----
__global__ __launch_bounds__(256) void pack_bias_k(const float* __restrict__ b0,
                                                   const float* __restrict__ b1,
                                                   const float* __restrict__ b2,
                                                   float* __restrict__ out)
{
    int i = blockIdx.x * 256 + threadIdx.x;
    out[i] = (i < DIM) ? b0[i] : (i < 2 * DIM) ? b1[i - DIM] : b2[i - 2 * DIM];
}

// ---- in-place LayerNorm over rows of 1024 fp32 ----
__global__ __launch_bounds__(256) void ln_k(float* __restrict__ y,
                                            const float* __restrict__ gamma,
                                            const float* __restrict__ beta)
{
    float* p = y + (long)blockIdx.x * DIM;
    const int tid = threadIdx.x;
    float4 v = reinterpret_cast<float4*>(p)[tid];
    float s  = v.x + v.y + v.z + v.w;
    float sq = v.x * v.x + v.y * v.y + v.z * v.z + v.w * v.w;
#pragma unroll
    for (int o = 16; o; o >>= 1) {
        s  += __shfl_xor_sync(0xFFFFFFFFu, s, o);
        sq += __shfl_xor_sync(0xFFFFFFFFu, sq, o);
    }
    __shared__ float rs_[8], rq_[8];
    if ((tid & 31) == 0) { rs_[tid >> 5] = s; rq_[tid >> 5] = sq; }
    __syncthreads();
    s = 0.f; sq = 0.f;
#pragma unroll
    for (int i = 0; i < 8; i++) { s += rs_[i]; sq += rq_[i]; }
    const float mean = s * (1.f / DIM);
    const float var  = sq * (1.f / DIM) - mean * mean;
    const float inv  = rsqrtf(var + 1e-5f);
    const float4 g = reinterpret_cast<const float4*>(gamma)[tid];
    const float4 b = reinterpret_cast<const float4*>(beta)[tid];
    v.x = (v.x - mean) * inv * g.x + b.x;
    v.y = (v.y - mean) * inv * g.y + b.y;
    v.z = (v.z - mean) * inv * g.z + b.z;
    v.w = (v.w - mean) * inv * g.w + b.w;
    reinterpret_cast<float4*>(p)[tid] = v;
}

extern "C" void kernel_launch(void* const* d_in, const int* in_sizes, int n_in,
                              void* d_out, int out_size)
{
    const float* x     = (const float*)d_in[0];
    const float* Wq    = (const float*)d_in[1];
    const float* bq    = (const float*)d_in[2];
    const float* Wk    = (const float*)d_in[3];
    const float* bk    = (const float*)d_in[4];
    const float* Wv    = (const float*)d_in[5];
    const float* bv    = (const float*)d_in[6];
    const float* Wo    = (const float*)d_in[7];
    const float* bo    = (const float*)d_in[8];
    const float* gamma = (const float*)d_in[9];
    const float* beta  = (const float*)d_in[10];
    float* out = (float*)d_out;

    void *pxb, *pwqkv, *pwo, *pbqkv, *pQKV, *pP, *pW, *prp, *pri;
    cudaGetSymbolAddress(&pxb,   g_xb);
    cudaGetSymbolAddress(&pwqkv, g_Wqkvb);
    cudaGetSymbolAddress(&pwo,   g_Wob);
    cudaGetSymbolAddress(&pbqkv, g_bqkv);
    cudaGetSymbolAddress(&pQKV,  g_QKV);
    cudaGetSymbolAddress(&pP,    g_P);
    cudaGetSymbolAddress(&pW,    g_Wt);
    cudaGetSymbolAddress(&prp,   g_rpart);
    cudaGetSymbolAddress(&pri,   g_rinv);
    __nv_bfloat16* xb    = (__nv_bfloat16*)pxb;
    __nv_bfloat16* Wqkvb = (__nv_bfloat16*)pwqkv;
    __nv_bfloat16* Wob   = (__nv_bfloat16*)pwo;
    float*         bqkv  = (float*)pbqkv;
    __nv_bfloat16* QKV   = (__nv_bfloat16*)pQKV;
    __nv_bfloat16* P     = (__nv_bfloat16*)pP;
    __nv_bfloat16* Wt    = (__nv_bfloat16*)pW;
    float*         rpart = (float*)prp;
    float*         rinv  = (float*)pri;

    const int SMEM = STAGES * STAGE_BYTES;  // 110592
    cudaFuncSetAttribute((const void*)gemm_bf<__nv_bfloat16, true,  false, true,  false, false>, cudaFuncAttributeMaxDynamicSharedMemorySize, SMEM);
    cudaFuncSetAttribute((const void*)gemm_bf<__nv_bfloat16, false, false, true,  true,  false>, cudaFuncAttributeMaxDynamicSharedMemorySize, SMEM);
    cudaFuncSetAttribute((const void*)gemm_bf<__nv_bfloat16, false, false, false, false, true >, cudaFuncAttributeMaxDynamicSharedMemorySize, SMEM);
    cudaFuncSetAttribute((const void*)gemm_bf<float,         true,  true,  true,  false, false>, cudaFuncAttributeMaxDynamicSharedMemorySize, SMEM);

    dim3 blk(128);
    dim3 blk256(256);

    // setup
    {
        int n = MTOT * DIM;
        cvt_k<<<(n / 4 + 255) / 256, blk256>>>(x, xb, n);
        cvt_w3_k<<<3 * DIM * DIM / 4 / 256, blk256>>>(Wq, Wk, Wv, Wqkvb);
        cvt_k<<<DIM * DIM / 4 / 256, blk256>>>(Wo, Wob, DIM * DIM);
        pack_bias_k<<<NQKV / 256, blk256>>>(bq, bk, bv, bqkv);
    }

    // fused QKV projection (bf16 out)
    dim3 gQKV(NQKV / BN, MTOT / BM, 1);
    gemm_bf<__nv_bfloat16, true, false, true, false, false><<<gQKV, blk, SMEM>>>(
        xb, Wqkvb, bqkv, nullptr, QKV, DIM, DIM, NQKV, DIM, 1.f, 0, 0, 0, nullptr, nullptr);

    const __nv_bfloat16* Qv = QKV;
    const __nv_bfloat16* Kv = QKV + DIM;
    const __nv_bfloat16* Vv = QKV + 2 * DIM;

    // P_unnorm = exp(Q K^T / 32) (bf16) + per-row tile sums
    dim3 gS_(SEQ / BN, SEQ / BM, BATCH);
    gemm_bf<__nv_bfloat16, false, false, true, true, false><<<gS_, blk, SMEM>>>(
        Qv, Kv, nullptr, nullptr, P, NQKV, NQKV, SEQ, DIM, 0.03125f,
        (long)SEQ * NQKV, (long)SEQ * NQKV, (long)SEQ * SEQ, rpart, nullptr);

    // rinv = 1 / row sums
    rowinv_k<<<MTOT / 256, blk256>>>(rpart, rinv);

    // weighted = (P_unnorm @ V) * rinv (NN path)
    dim3 gW_(DIM / BN, SEQ / BM, BATCH);
    gemm_bf<__nv_bfloat16, false, false, false, false, true><<<gW_, blk, SMEM>>>(
        P, Vv, nullptr, nullptr, Wt, SEQ, NQKV, DIM, SEQ, 1.f,
        (long)SEQ * SEQ, (long)SEQ * NQKV, (long)SEQ * DIM, nullptr, rinv);

    // out = weighted Wo^T + bo + x (fp32, residual fused)
    dim3 gO_(DIM / BN, MTOT / BM, 1);
    gemm_bf<float, true, true, true, false, false><<<gO_, blk, SMEM>>>(
        Wt, Wob, bo, x, out, DIM, DIM, DIM, DIM, 1.f, 0, 0, 0, nullptr, nullptr);

    // LayerNorm
    ln_k<<<MTOT, blk256>>>(out, gamma, beta);
}

// round 17
// speedup vs baseline: 1.0375x; 1.0117x over previous
#include <cuda_runtime.h>
#include <cuda_bf16.h>
#include <cstdint>
#include <cstddef>

#define BATCH 8
#define SEQ   2048
#define DIM   1024
#define MTOT  (BATCH*SEQ)   // 16384
#define NQKV  (3*DIM)       // 3072
#define KTILES (SEQ/128)    // 16 k-tiles per attention row

#define BM 128
#define BN 128
#define BK 64
#define KSTRIDE 72                        // NT: halves per smem row (64 data + 8 pad)
#define NSTRIDE 136                       // NN B tile: 128 cols + 8 pad
#define A_TILE_HALVES (BM*KSTRIDE)        // 9216
#define STAGE_HALVES (2*A_TILE_HALVES)
#define STAGE_BYTES (STAGE_HALVES*2)      // 36864
#define STAGES 3
#define SMEM_GEMM (STAGES*STAGE_BYTES + 512)   // +512B rinv_s slot

// ---- scratch (device globals; allocation-free per harness rules) ----
__device__ __nv_bfloat16 g_xb[(size_t)MTOT*DIM];
__device__ __nv_bfloat16 g_Wqkvb[(size_t)NQKV*DIM];
__device__ __nv_bfloat16 g_Wob[DIM*DIM];
__device__ float         g_bqkv[NQKV];
__device__ __nv_bfloat16 g_QKV[(size_t)MTOT*NQKV];
__device__ __nv_bfloat16 g_P [(size_t)BATCH*SEQ*SEQ];
__device__ float         g_rpart[(size_t)BATCH*KTILES*SEQ];
__device__ __nv_bfloat16 g_Wt[(size_t)MTOT*DIM];

// ---- helpers ----
__device__ __forceinline__ void cp16(uint32_t saddr, const void* gmem) {
    asm volatile("cp.async.cg.shared.global [%0], [%1], 16;\n" :: "r"(saddr), "l"(gmem));
}
__device__ __forceinline__ void cp_commit() { asm volatile("cp.async.commit_group;\n"); }
template<int N> __device__ __forceinline__ void cp_wait() {
    asm volatile("cp.async.wait_group %0;\n" :: "n"(N));
}
__device__ __forceinline__ void ldsm_x4(uint32_t& r0, uint32_t& r1, uint32_t& r2, uint32_t& r3,
                                        uint32_t addr) {
    asm volatile("ldmatrix.sync.aligned.m8n8.x4.shared.b16 {%0,%1,%2,%3}, [%4];"
                 : "=r"(r0), "=r"(r1), "=r"(r2), "=r"(r3) : "r"(addr));
}
__device__ __forceinline__ void ldsm_x4_t(uint32_t& r0, uint32_t& r1, uint32_t& r2, uint32_t& r3,
                                          uint32_t addr) {
    asm volatile("ldmatrix.sync.aligned.m8n8.x4.trans.shared.b16 {%0,%1,%2,%3}, [%4];"
                 : "=r"(r0), "=r"(r1), "=r"(r2), "=r"(r3) : "r"(addr));
}
__device__ __forceinline__ void mma_bf16(float c[4], const uint32_t a[4], const uint32_t b[2]) {
    asm("mma.sync.aligned.m16n8k16.row.col.f32.bf16.bf16.f32 "
        "{%0,%1,%2,%3},{%4,%5,%6,%7},{%8,%9},{%0,%1,%2,%3};"
        : "+f"(c[0]), "+f"(c[1]), "+f"(c[2]), "+f"(c[3])
        : "r"(a[0]), "r"(a[1]), "r"(a[2]), "r"(a[3]), "r"(b[0]), "r"(b[1]));
}

// ---- bf16 GEMM: C = f(A[M,K] * op(B) * scale) (+bias) (+resid) ----
// TRANSB: B [N,K] (NT) vs [K,N] (NN, ldmatrix.trans).
// EXP_OUT: C = exp(v), deterministic per-row tile sums -> rpart.
// ROW_DIV: C = v / rowsum; rowsum computed in-kernel from rpart (prologue).
template<typename OutT, bool HAS_BIAS, bool HAS_RESID, bool TRANSB, bool EXP_OUT, bool ROW_DIV>
__global__ __launch_bounds__(128, 2) void gemm_bf(
    const __nv_bfloat16* __restrict__ A, const __nv_bfloat16* __restrict__ B,
    const float* __restrict__ bias, const float* __restrict__ resid,
    OutT* __restrict__ C,
    int lda, int ldb, int ldc, int K, float scale,
    long sA, long sB, long sC,
    float* __restrict__ rpart, const float* __restrict__ rpart_in)
{
    extern __shared__ __align__(16) __nv_bfloat16 smem[];  // STAGES*(As+Bs) + rinv_s

    const int bz = blockIdx.z;
    A += (long)bz * sA;
    B += (long)bz * sB;
    C += (long)bz * sC;

    const int m0 = blockIdx.y * BM;
    const int n0 = blockIdx.x * BN;
    const int tid  = threadIdx.x;
    const int wid  = tid >> 5;
    const int lane = tid & 31;
    const int wm = (wid >> 1) * 64;   // 2 warps in m
    const int wn = (wid & 1) * 64;    // 2 warps in n
    const int lg = lane >> 2;
    const int lq = lane & 3;

    const int lr = tid >> 3;          // NT loader: 8 thr/row
    const int lc = (tid & 7) * 8;
    const int lr16 = tid >> 4;        // NN B loader: 16 thr/row
    const int lc16 = (tid & 15) * 8;

    const int a_row = wm + (lane & 15);
    const int a_ksel = (lane >> 4) * 8;
    const int b_row = wn + (lane & 7) + ((lane >> 4) & 1) * 8;
    const int b_ksel = ((lane >> 3) & 1) * 8;
    const int bt_krow = (lane & 7) + ((lane >> 3) & 1) * 8;
    const int bt_ncol = wn + ((lane >> 4) & 1) * 8;

    const uint32_t smem_base = (uint32_t)__cvta_generic_to_shared(smem);
    float* rinv_s = reinterpret_cast<float*>(
        reinterpret_cast<char*>(smem) + STAGES * STAGE_BYTES);

    float acc[4][8][4];
#pragma unroll
    for (int i = 0; i < 4; i++)
#pragma unroll
        for (int j = 0; j < 8; j++)
#pragma unroll
            for (int r = 0; r < 4; r++) acc[i][j][r] = 0.f;

    const int KT = K / BK;

    auto load_stage = [&](int buf, int kt) {
        const int k0 = kt * BK;
        const uint32_t as = smem_base + buf * STAGE_BYTES;
        const uint32_t bs = as + A_TILE_HALVES * 2;
#pragma unroll
        for (int p = 0; p < 8; p++) {
            int row = lr + p * 16;
            cp16(as + (row * KSTRIDE + lc) * 2, A + (long)(m0 + row) * lda + k0 + lc);
        }
        if (TRANSB) {
#pragma unroll
            for (int p = 0; p < 8; p++) {
                int row = lr + p * 16;
                cp16(bs + (row * KSTRIDE + lc) * 2, B + (long)(n0 + row) * ldb + k0 + lc);
            }
        } else {
#pragma unroll
            for (int p = 0; p < 8; p++) {
                int row = lr16 + p * 8;
                cp16(bs + (row * NSTRIDE + lc16) * 2, B + (long)(k0 + row) * ldb + n0 + lc16);
            }
        }
        cp_commit();
    };

    load_stage(0, 0);
    load_stage(1, 1);

    // ROW_DIV prologue: compute 1/rowsum for this CTA's 128 rows (overlaps cp.async)
    if (ROW_DIV && tid < 128) {
        float s = 0.f;
#pragma unroll
        for (int t = 0; t < KTILES; t++)
            s += rpart_in[((long)bz * KTILES + t) * SEQ + m0 + tid];
        rinv_s[tid] = 1.f / s;
    }
    // visibility of rinv_s guaranteed by the first loop-iteration __syncthreads

    // double-buffered fragments
    uint32_t af[2][4][4];
    uint32_t bfr[2][8][2];

    auto load_frags = [&](uint32_t as, uint32_t bs, int s, int pb) {
#pragma unroll
        for (int i = 0; i < 4; i++) {
            uint32_t addr = as + (((a_row + i * 16) * KSTRIDE) + s * 16 + a_ksel) * 2;
            ldsm_x4(af[pb][i][0], af[pb][i][1], af[pb][i][2], af[pb][i][3], addr);
        }
#pragma unroll
        for (int jp = 0; jp < 4; jp++) {
            if (TRANSB) {
                uint32_t addr = bs + (((b_row + jp * 16) * KSTRIDE) + s * 16 + b_ksel) * 2;
                ldsm_x4(bfr[pb][jp * 2][0], bfr[pb][jp * 2][1],
                        bfr[pb][jp * 2 + 1][0], bfr[pb][jp * 2 + 1][1], addr);
            } else {
                uint32_t addr = bs + (((s * 16 + bt_krow) * NSTRIDE) + bt_ncol + jp * 16) * 2;
                ldsm_x4_t(bfr[pb][jp * 2][0], bfr[pb][jp * 2][1],
                          bfr[pb][jp * 2 + 1][0], bfr[pb][jp * 2 + 1][1], addr);
            }
        }
    };

    for (int kt = 0; kt < KT; kt++) {
        const int buf = kt % STAGES;
        cp_wait<1>();
        __syncthreads();

        if (kt + 2 < KT) load_stage((kt + 2) % STAGES, kt + 2);

        const uint32_t as = smem_base + buf * STAGE_BYTES;
        const uint32_t bs = as + A_TILE_HALVES * 2;

        load_frags(as, bs, 0, 0);
#pragma unroll
        for (int s = 0; s < 4; s++) {
            const int cur = s & 1;
            if (s < 3) load_frags(as, bs, s + 1, cur ^ 1);
#pragma unroll
            for (int i = 0; i < 4; i++)
#pragma unroll
                for (int j = 0; j < 8; j++)
                    mma_bf16(acc[i][j], af[cur][i], bfr[cur][j]);
        }
    }

    // epilogue
    float rs0[4], rs1[4];
#pragma unroll
    for (int i = 0; i < 4; i++) { rs0[i] = 0.f; rs1[i] = 0.f; }

#pragma unroll
    for (int i = 0; i < 4; i++) {
        int r = m0 + wm + i * 16 + lg;
        float ri0 = 1.f, ri1 = 1.f;
        if (ROW_DIV) {
            ri0 = rinv_s[wm + i * 16 + lg];
            ri1 = rinv_s[wm + i * 16 + lg + 8];
        }
#pragma unroll
        for (int j = 0; j < 8; j++) {
            int c = n0 + wn + j * 8 + lq * 2;
            float v0 = acc[i][j][0] * scale;
            float v1 = acc[i][j][1] * scale;
            float v2 = acc[i][j][2] * scale;
            float v3 = acc[i][j][3] * scale;
            if (HAS_BIAS) {
                float b0 = bias[c], b1 = bias[c + 1];
                v0 += b0; v1 += b1; v2 += b0; v3 += b1;
            }
            if (HAS_RESID) {
                v0 += resid[(long)r * ldc + c];
                v1 += resid[(long)r * ldc + c + 1];
                v2 += resid[(long)(r + 8) * ldc + c];
                v3 += resid[(long)(r + 8) * ldc + c + 1];
            }
            if (EXP_OUT) {
                v0 = __expf(v0); v1 = __expf(v1);
                v2 = __expf(v2); v3 = __expf(v3);
                rs0[i] += v0 + v1;
                rs1[i] += v2 + v3;
            }
            if (ROW_DIV) {
                v0 *= ri0; v1 *= ri0;
                v2 *= ri1; v3 *= ri1;
            }
            if constexpr (sizeof(OutT) == 2) {
                *reinterpret_cast<__nv_bfloat162*>(&C[(long)r * ldc + c]) =
                    __floats2bfloat162_rn(v0, v1);
                *reinterpret_cast<__nv_bfloat162*>(&C[(long)(r + 8) * ldc + c]) =
                    __floats2bfloat162_rn(v2, v3);
            } else {
                *reinterpret_cast<float2*>(&C[(long)r * ldc + c])       = make_float2(v0, v1);
                *reinterpret_cast<float2*>(&C[(long)(r + 8) * ldc + c]) = make_float2(v2, v3);
            }
        }
    }

    if (EXP_OUT) {
        // deterministic per-row tile sums: smem [128 rows][8 slots]
        float* sf = reinterpret_cast<float*>(smem);
        const int slot = (wid & 1) * 4 + lq;
        __syncthreads();   // done with pipeline smem
#pragma unroll
        for (int i = 0; i < 4; i++) {
            int rr = wm + i * 16 + lg;
            sf[rr * 8 + slot]       = rs0[i];
            sf[(rr + 8) * 8 + slot] = rs1[i];
        }
        __syncthreads();
        if (tid < 128) {
            float s = 0.f;
#pragma unroll
            for (int k = 0; k < 8; k++) s += sf[tid * 8 + k];
            rpart[((long)bz * gridDim.x + blockIdx.x) * SEQ + m0 + tid] = s;
        }
    }
}

// ---- one fused setup kernel: cvt x, cvt Wq|Wk|Wv, cvt Wo, pack bias ----
#define NB_X  (MTOT*DIM/1024)        // 16384 blocks
#define NB_W3 (3*DIM*DIM/1024)       // 3072
#define NB_WO (DIM*DIM/1024)         // 1024
#define NB_B  (NQKV/256)             // 12
__global__ __launch_bounds__(256) void setup_k(
    const float* __restrict__ x,
    const float* __restrict__ Wq, const float* __restrict__ Wk,
    const float* __restrict__ Wv, const float* __restrict__ Wo,
    const float* __restrict__ bq, const float* __restrict__ bk,
    const float* __restrict__ bv,
    __nv_bfloat16* __restrict__ xb, __nv_bfloat16* __restrict__ Wqkvb,
    __nv_bfloat16* __restrict__ Wob, float* __restrict__ bqkv)
{
    const int b = blockIdx.x;
    if (b < NB_X + NB_W3 + NB_WO) {
        const float* src;
        __nv_bfloat16* dst;
        long i;
        if (b < NB_X) {
            src = x; dst = xb;
            i = ((long)b * 256 + threadIdx.x) * 4;
        } else if (b < NB_X + NB_W3) {
            int bb = b - NB_X;
            int per = DIM * DIM / 1024;           // 1024 blocks per matrix
            int mat = bb / per;
            src = (mat == 0) ? Wq : (mat == 1) ? Wk : Wv;
            dst = Wqkvb + (size_t)mat * DIM * DIM;
            i = ((long)(bb % per) * 256 + threadIdx.x) * 4;
        } else {
            src = Wo; dst = Wob;
            i = ((long)(b - NB_X - NB_W3) * 256 + threadIdx.x) * 4;
        }
        float4 v = *reinterpret_cast<const float4*>(src + i);
        *reinterpret_cast<__nv_bfloat162*>(dst + i)     = __floats2bfloat162_rn(v.x, v.y);
        *reinterpret_cast<__nv_bfloat162*>(dst + i + 2) = __floats2bfloat162_rn(v.z, v.w);
    } else {
        int i = (b - NB_X - NB_W3 - NB_WO) * 256 + threadIdx.x;   // 0..3071
        bqkv[i] = (i < DIM) ? bq[i] : (i < 2 * DIM) ? bk[i - DIM] : bv[i - 2 * DIM];
    }
}

// ---- in-place LayerNorm over rows of 1024 fp32 ----
__global__ __launch_bounds__(256) void ln_k(float* __restrict__ y,
                                            const float* __restrict__ gamma,
                                            const float* __restrict__ beta)
{
    float* p = y + (long)blockIdx.x * DIM;
    const int tid = threadIdx.x;
    float4 v = reinterpret_cast<float4*>(p)[tid];
    float s  = v.x + v.y + v.z + v.w;
    float sq = v.x * v.x + v.y * v.y + v.z * v.z + v.w * v.w;
#pragma unroll
    for (int o = 16; o; o >>= 1) {
        s  += __shfl_xor_sync(0xFFFFFFFFu, s, o);
        sq += __shfl_xor_sync(0xFFFFFFFFu, sq, o);
    }
    __shared__ float rs_[8], rq_[8];
    if ((tid & 31) == 0) { rs_[tid >> 5] = s; rq_[tid >> 5] = sq; }
    __syncthreads();
    s = 0.f; sq = 0.f;
#pragma unroll
    for (int i = 0; i < 8; i++) { s += rs_[i]; sq += rq_[i]; }
    const float mean = s * (1.f / DIM);
    const float var  = sq * (1.f / DIM) - mean * mean;
    const float inv  = rsqrtf(var + 1e-5f);
    const float4 g = reinterpret_cast<const float4*>(gamma)[tid];
    const float4 b = reinterpret_cast<const float4*>(beta)[tid];
    v.x = (v.x - mean) * inv * g.x + b.x;
    v.y = (v.y - mean) * inv * g.y + b.y;
    v.z = (v.z - mean) * inv * g.z + b.z;
    v.w = (v.w - mean) * inv * g.w + b.w;
    reinterpret_cast<float4*>(p)[tid] = v;
}

extern "C" void kernel_launch(void* const* d_in, const int* in_sizes, int n_in,
                              void* d_out, int out_size)
{
    const float* x     = (const float*)d_in[0];
    const float* Wq    = (const float*)d_in[1];
    const float* bq    = (const float*)d_in[2];
    const float* Wk    = (const float*)d_in[3];
    const float* bk    = (const float*)d_in[4];
    const float* Wv    = (const float*)d_in[5];
    const float* bv    = (const float*)d_in[6];
    const float* Wo    = (const float*)d_in[7];
    const float* bo    = (const float*)d_in[8];
    const float* gamma = (const float*)d_in[9];
    const float* beta  = (const float*)d_in[10];
    float* out = (float*)d_out;

    void *pxb, *pwqkv, *pwo, *pbqkv, *pQKV, *pP, *pW, *prp;
    cudaGetSymbolAddress(&pxb,   g_xb);
    cudaGetSymbolAddress(&pwqkv, g_Wqkvb);
    cudaGetSymbolAddress(&pwo,   g_Wob);
    cudaGetSymbolAddress(&pbqkv, g_bqkv);
    cudaGetSymbolAddress(&pQKV,  g_QKV);
    cudaGetSymbolAddress(&pP,    g_P);
    cudaGetSymbolAddress(&pW,    g_Wt);
    cudaGetSymbolAddress(&prp,   g_rpart);
    __nv_bfloat16* xb    = (__nv_bfloat16*)pxb;
    __nv_bfloat16* Wqkvb = (__nv_bfloat16*)pwqkv;
    __nv_bfloat16* Wob   = (__nv_bfloat16*)pwo;
    float*         bqkv  = (float*)pbqkv;
    __nv_bfloat16* QKV   = (__nv_bfloat16*)pQKV;
    __nv_bfloat16* P     = (__nv_bfloat16*)pP;
    __nv_bfloat16* Wt    = (__nv_bfloat16*)pW;
    float*         rpart = (float*)prp;

    cudaFuncSetAttribute((const void*)gemm_bf<__nv_bfloat16, true,  false, true,  false, false>, cudaFuncAttributeMaxDynamicSharedMemorySize, SMEM_GEMM);
    cudaFuncSetAttribute((const void*)gemm_bf<__nv_bfloat16, false, false, true,  true,  false>, cudaFuncAttributeMaxDynamicSharedMemorySize, SMEM_GEMM);
    cudaFuncSetAttribute((const void*)gemm_bf<__nv_bfloat16, false, false, false, false, true >, cudaFuncAttributeMaxDynamicSharedMemorySize, SMEM_GEMM);
    cudaFuncSetAttribute((const void*)gemm_bf<float,         true,  true,  true,  false, false>, cudaFuncAttributeMaxDynamicSharedMemorySize, SMEM_GEMM);

    dim3 blk(128);
    dim3 blk256(256);

    // 1) fused setup (single launch)
    setup_k<<<NB_X + NB_W3 + NB_WO + NB_B, blk256>>>(
        x, Wq, Wk, Wv, Wo, bq, bk, bv, xb, Wqkvb, Wob, bqkv);

    // 2) fused QKV projection (bf16 out)
    dim3 gQKV(NQKV / BN, MTOT / BM, 1);
    gemm_bf<__nv_bfloat16, true, false, true, false, false><<<gQKV, blk, SMEM_GEMM>>>(
        xb, Wqkvb, bqkv, nullptr, QKV, DIM, DIM, NQKV, DIM, 1.f, 0, 0, 0, nullptr, nullptr);

    const __nv_bfloat16* Qv = QKV;
    const __nv_bfloat16* Kv = QKV + DIM;
    const __nv_bfloat16* Vv = QKV + 2 * DIM;

    // 3) P_unnorm = exp(Q K^T / 32) (bf16) + per-row tile sums
    dim3 gS_(SEQ / BN, SEQ / BM, BATCH);
    gemm_bf<__nv_bfloat16, false, false, true, true, false><<<gS_, blk, SMEM_GEMM>>>(
        Qv, Kv, nullptr, nullptr, P, NQKV, NQKV, SEQ, DIM, 0.03125f,
        (long)SEQ * NQKV, (long)SEQ * NQKV, (long)SEQ * SEQ, rpart, nullptr);

    // 4) weighted = (P_unnorm @ V) / rowsum  (NN path; rowsum from rpart in-kernel)
    dim3 gW_(DIM / BN, SEQ / BM, BATCH);
    gemm_bf<__nv_bfloat16, false, false, false, false, true><<<gW_, blk, SMEM_GEMM>>>(
        P, Vv, nullptr, nullptr, Wt, SEQ, NQKV, DIM, SEQ, 1.f,
        (long)SEQ * SEQ, (long)SEQ * NQKV, (long)SEQ * DIM, nullptr, rpart);

    // 5) out = weighted Wo^T + bo + x (fp32, residual fused)
    dim3 gO_(DIM / BN, MTOT / BM, 1);
    gemm_bf<float, true, true, true, false, false><<<gO_, blk, SMEM_GEMM>>>(
        Wt, Wob, bo, x, out, DIM, DIM, DIM, DIM, 1.f, 0, 0, 0, nullptr, nullptr);

    // 6) LayerNorm
    ln_k<<<MTOT, blk256>>>(out, gamma, beta);
}